// round 14
// baseline (speedup 1.0000x reference)
#include <cuda_runtime.h>
#include <cuda_fp16.h>
#include <cstdint>

#define B_DIM 1024
#define Z_DIM 32768
#define D_DIM 128

constexpr int NCTA = 148;     // one exact wave
constexpr int NJOBS = 2048;   // job j -> (bt = j>>8, zt = j&255)
constexpr int THREADS = 256;  // 8 warps x 16-row bands
constexpr float SCALE2 = 0.088388347648318447f * 1.4426950408889634f;  // rsqrt(128)*log2(e)

constexpr int MASK_P = 132;
constexpr int MASK_BUF = 128 * MASK_P;          // 16896
// smem: 4-stage emb fp16 (PV lags one job), ctx fp16, 3-stage byte mask
constexpr int SM_EMB  = 0;                      // 4 x 32768 = 131072
constexpr int SM_CTX  = 131072;                 // 32768
constexpr int SM_MASK = 163840;                 // 3 x 16896 = 50688
constexpr int SM_TOTAL = SM_MASK + 3 * MASK_BUF;   // 214528

__device__ uint32_t g_emb16[Z_DIM * D_DIM / 2];    // fp16x2 table, 8 MB
// per-segment partials: slot = 2*cta + seg
__device__ float g_pacc[2 * NCTA * 128 * D_DIM];   // 19.4 MB
__device__ float g_pss[2 * NCTA * 128];
__device__ int   g_pcnt[2 * NCTA * 128];

__device__ __forceinline__ uint32_t smem_u32(const void* p) {
    uint32_t a;
    asm("{ .reg .u64 t; cvta.to.shared.u64 t, %1; cvt.u32.u64 %0, t; }" : "=r"(a) : "l"(p));
    return a;
}
__device__ __forceinline__ uint32_t pk(float lo, float hi) {
    uint32_t r;
    asm("cvt.rn.f16x2.f32 %0, %1, %2;" : "=r"(r) : "f"(hi), "f"(lo));
    return r;
}
__device__ __forceinline__ uint32_t ex2h2(uint32_t x) {
    uint32_t y;
    asm("ex2.approx.f16x2 %0, %1;" : "=r"(y) : "r"(x));
    return y;
}
__device__ __forceinline__ uint32_t hadd2(uint32_t a, uint32_t b) {
    uint32_t y;
    asm("add.rn.f16x2 %0, %1, %2;" : "=r"(y) : "r"(a), "r"(b));
    return y;
}
__device__ __forceinline__ uint32_t prmt_sign(uint32_t m) {
    uint32_t y;
    asm("prmt.b32 %0, %1, 0, 0x9988;" : "=r"(y) : "r"(m));
    return y;
}
__device__ __forceinline__ void ldsm4(uint32_t& r0, uint32_t& r1, uint32_t& r2, uint32_t& r3,
                                      uint32_t a) {
    asm volatile("ldmatrix.sync.aligned.m8n8.x4.shared.b16 {%0,%1,%2,%3}, [%4];"
                 : "=r"(r0), "=r"(r1), "=r"(r2), "=r"(r3) : "r"(a));
}
__device__ __forceinline__ void ldsm4t(uint32_t& r0, uint32_t& r1, uint32_t& r2, uint32_t& r3,
                                       uint32_t a) {
    asm volatile("ldmatrix.sync.aligned.m8n8.x4.trans.shared.b16 {%0,%1,%2,%3}, [%4];"
                 : "=r"(r0), "=r"(r1), "=r"(r2), "=r"(r3) : "r"(a));
}
__device__ __forceinline__ void mma16816(float* c, const uint32_t* a, uint32_t b0, uint32_t b1) {
    asm volatile("mma.sync.aligned.m16n8k16.row.col.f32.f16.f16.f32 "
                 "{%0,%1,%2,%3}, {%4,%5,%6,%7}, {%8,%9}, {%0,%1,%2,%3};"
                 : "+f"(c[0]), "+f"(c[1]), "+f"(c[2]), "+f"(c[3])
                 : "r"(a[0]), "r"(a[1]), "r"(a[2]), "r"(a[3]), "r"(b0), "r"(b1));
}
__device__ __forceinline__ void mma16816h(uint32_t* c, const uint32_t* a, uint32_t b0, uint32_t b1) {
    asm volatile("mma.sync.aligned.m16n8k16.row.col.f16.f16.f16.f16 "
                 "{%0,%1}, {%2,%3,%4,%5}, {%6,%7}, {%0,%1};"
                 : "+r"(c[0]), "+r"(c[1])
                 : "r"(a[0]), "r"(a[1]), "r"(a[2]), "r"(a[3]), "r"(b0), "r"(b1));
}
__device__ __forceinline__ void cp16(uint32_t dst, const void* src) {
    asm volatile("cp.async.cg.shared.global [%0], [%1], 16;" :: "r"(dst), "l"(src));
}

// fp32 table -> fp16 (linear layout), one uint4 per thread (measured-best shape)
__global__ void conv_emb(const float* __restrict__ emb) {
    int f = blockIdx.x * 256 + threadIdx.x;          // 524288 threads
    const float4* s = reinterpret_cast<const float4*>(emb) + (size_t)f * 2;
    float4 v0 = s[0], v1 = s[1];
    uint4 o;
    o.x = pk(v0.x, v0.y); o.y = pk(v0.z, v0.w);
    o.z = pk(v1.x, v1.y); o.w = pk(v1.z, v1.w);
    reinterpret_cast<uint4*>(g_emb16)[f] = o;
}

__global__ __launch_bounds__(THREADS, 1) void stage2_mma(
    const int* __restrict__ zs, const float* __restrict__ ctx)
{
    extern __shared__ __align__(128) char smem[];
    const uint32_t sb = smem_u32(smem);
    const int tid = threadIdx.x, w = tid >> 5, lane = tid & 31;
    const int cta = blockIdx.x;
    const int j0 = (cta * NJOBS) / NCTA;
    const int j1 = ((cta + 1) * NJOBS) / NCTA;
    const int wrow0 = w * 16;
    const int sub = lane >> 3, l7 = lane & 7;
    const int g = lane >> 2, tq = lane & 3;
    const char* embg = reinterpret_cast<const char*>(g_emb16);

    int bt = j0 >> 8;
    int seg = 0;

    // ---- prologue: emb(j0)->e0, emb(j0+1)->e1 (2 commit groups), mask(j0)->m0, ctx
#pragma unroll
    for (int it = 0; it < 8; it++) {
        int f = it * THREADS + tid, r = f >> 4, c = f & 15;
        cp16(sb + SM_EMB + r * 256 + ((c ^ (r & 7)) << 4),
             embg + ((size_t)(j0 & 255) * 128 + r) * 256 + c * 16);
    }
    asm volatile("cp.async.commit_group;" ::: "memory");
    if (j0 + 1 < j1) {
#pragma unroll
        for (int it = 0; it < 8; it++) {
            int f = it * THREADS + tid, r = f >> 4, c = f & 15;
            cp16(sb + SM_EMB + 32768 + r * 256 + ((c ^ (r & 7)) << 4),
                 embg + ((size_t)((j0 + 1) & 255) * 128 + r) * 256 + c * 16);
        }
    }
    asm volatile("cp.async.commit_group;" ::: "memory");
#pragma unroll
    for (int it = 0; it < 16; it++) {
        int row = it * 8 + w;
        int4 m = *reinterpret_cast<const int4*>(
            &zs[(size_t)((bt << 7) + row) * Z_DIM + (j0 & 255) * 128 + lane * 4]);
        uchar4 mb;
        mb.x = (m.x > 0) ? 0xFFu : 0u; mb.y = (m.y > 0) ? 0xFFu : 0u;
        mb.z = (m.z > 0) ? 0xFFu : 0u; mb.w = (m.w > 0) ? 0xFFu : 0u;
        *reinterpret_cast<uchar4*>(smem + SM_MASK + row * MASK_P + lane * 4) = mb;
    }
#pragma unroll
    for (int it = 0; it < 8; it++) {
        int f = it * THREADS + tid, r = f >> 4, c = f & 15;
        const float4* s = reinterpret_cast<const float4*>(
            &ctx[(size_t)((bt << 7) + r) * D_DIM + c * 8]);
        float4 v0 = s[0], v1 = s[1];
        uint4 o;
        o.x = pk(v0.x * SCALE2, v0.y * SCALE2); o.y = pk(v0.z * SCALE2, v0.w * SCALE2);
        o.z = pk(v1.x * SCALE2, v1.y * SCALE2); o.w = pk(v1.z * SCALE2, v1.w * SCALE2);
        *reinterpret_cast<uint4*>(smem + SM_CTX + r * 256 + ((c ^ (r & 7)) << 4)) = o;
    }
    __syncthreads();

    uint32_t aCtx[8][4];
#pragma unroll
    for (int kk = 0; kk < 8; kk++) {
        int rm = wrow0 + ((sub & 1) << 3) + l7;
        int ch = 2 * kk + (sub >> 1);
        ldsm4(aCtx[kk][0], aCtx[kk][1], aCtx[kk][2], aCtx[kk][3],
              sb + SM_CTX + rm * 256 + ((ch ^ (rm & 7)) << 4));
    }

    float o[16][4];
#pragma unroll
    for (int i = 0; i < 16; i++)
#pragma unroll
        for (int jx = 0; jx < 4; jx++) o[i][jx] = 0.f;
    float ssum0 = 0.f, ssum1 = 0.f;
    int cnt0 = 0, cnt1 = 0;
    int es = 0;    // emb stage of job j (mod 4)
    int ms = 0;    // mask stage of job j (mod 3)
    int pend = 0;  // have deferred PV for job j-1 (W in wlo/whi, emb in stage (es+3)&3)
    uint32_t wlo[16], whi[16];

    for (int j = j0; j < j1; j++) {
        asm volatile("cp.async.wait_group 1;" ::: "memory");   // emb(j) landed
        __syncthreads();   // all warps done with stage being overwritten below

        // ---- prefetch (post-barrier => race-free): emb(j+2) -> (es+2)&3
        if (j + 2 < j1) {
            int ztn = (j + 2) & 255;
            uint32_t edst = sb + SM_EMB + ((es + 2) & 3) * 32768;
#pragma unroll
            for (int it = 0; it < 8; it++) {
                int f = it * THREADS + tid, r = f >> 4, c = f & 15;
                cp16(edst + r * 256 + ((c ^ (r & 7)) << 4),
                     embg + ((size_t)ztn * 128 + r) * 256 + c * 16);
            }
        }
        asm volatile("cp.async.commit_group;" ::: "memory");   // unconditional: keeps FIFO count
        // mask(j+1) -> stage (ms+1)%3
        if (j + 1 < j1) {
            int btn = (j + 1) >> 8, ztn = (j + 1) & 255;
            int msn = (ms == 2) ? 0 : ms + 1;
            char* mdst = smem + SM_MASK + msn * MASK_BUF;
#pragma unroll
            for (int it = 0; it < 16; it++) {
                int row = it * 8 + w;
                int4 m = *reinterpret_cast<const int4*>(
                    &zs[(size_t)((btn << 7) + row) * Z_DIM + ztn * 128 + lane * 4]);
                uchar4 mb;
                mb.x = (m.x > 0) ? 0xFFu : 0u; mb.y = (m.y > 0) ? 0xFFu : 0u;
                mb.z = (m.z > 0) ? 0xFFu : 0u; mb.w = (m.w > 0) ? 0xFFu : 0u;
                *reinterpret_cast<uchar4*>(&mdst[row * MASK_P + lane * 4]) = mb;
            }
        }

        const uint32_t eb  = sb + SM_EMB + es * 32768;             // emb(j)
        const uint32_t ebp = sb + SM_EMB + ((es + 3) & 3) * 32768; // emb(j-1)
        const unsigned char* mask_s =
            reinterpret_cast<const unsigned char*>(smem + SM_MASK + ms * MASK_BUF);

        // ---- S(j) = ctx @ emb(j)^T, fp16 accumulate
        uint32_t s[16][2];
#pragma unroll
        for (int i = 0; i < 16; i++) { s[i][0] = 0u; s[i][1] = 0u; }
#pragma unroll
        for (int kk = 0; kk < 8; kk++) {
#pragma unroll
            for (int G = 0; G < 8; G++) {
                int rz = G * 16 + ((sub >> 1) << 3) + l7;
                int ch = 2 * kk + (sub & 1);
                uint32_t r0, r1, r2, r3;
                ldsm4(r0, r1, r2, r3, eb + rz * 256 + ((ch ^ (rz & 7)) << 4));
                mma16816h(s[2 * G], aCtx[kk], r0, r1);
                mma16816h(s[2 * G + 1], aCtx[kk], r2, r3);
            }
        }

        // ---- deferred PV(j-1): independent of S(j)/epilogue(j) -> overlaps ex2 latency
        if (pend) {
#pragma unroll
            for (int kk = 0; kk < 8; kk++) {
                uint32_t aW[4] = { wlo[2 * kk], whi[2 * kk], wlo[2 * kk + 1], whi[2 * kk + 1] };
#pragma unroll
                for (int G = 0; G < 8; G++) {
                    int rz = kk * 16 + ((sub & 1) << 3) + l7;
                    int ch = 2 * G + (sub >> 1);
                    uint32_t r0, r1, r2, r3;
                    ldsm4t(r0, r1, r2, r3, ebp + rz * 256 + ((ch ^ (rz & 7)) << 4));
                    mma16816(o[2 * G], aW, r0, r1);
                    mma16816(o[2 * G + 1], aW, r2, r3);
                }
            }
        }

        // ---- epilogue(j): W(j) = ex2(S) & mask, in place
        const unsigned char* mrow0 = &mask_s[(wrow0 + g) * MASK_P];
        const unsigned char* mrow1 = mrow0 + 8 * MASK_P;
        uint32_t sa0 = 0, sa1 = 0;
#pragma unroll
        for (int f = 0; f < 16; f++) {
            int zb = 8 * f + 2 * tq;
            uint32_t m0 = *reinterpret_cast<const unsigned short*>(&mrow0[zb]);
            uint32_t m1 = *reinterpret_cast<const unsigned short*>(&mrow1[zb]);
            cnt0 += __popc(m0);
            cnt1 += __popc(m1);
            s[f][0] = ex2h2(s[f][0]) & prmt_sign(m0);
            s[f][1] = ex2h2(s[f][1]) & prmt_sign(m1);
            sa0 = hadd2(sa0, s[f][0]);
            sa1 = hadd2(sa1, s[f][1]);
        }
        {
            __half2 h0 = *reinterpret_cast<__half2*>(&sa0);
            __half2 h1 = *reinterpret_cast<__half2*>(&sa1);
            ssum0 += __low2float(h0) + __high2float(h0);
            ssum1 += __low2float(h1) + __high2float(h1);
        }

        bool lastjob = (j + 1 == j1);
        bool cross = !lastjob && (((j + 1) >> 8) != bt);
        if (!(lastjob || cross)) {
            // hand W(j) to next iteration's deferred PV
#pragma unroll
            for (int f = 0; f < 16; f++) { wlo[f] = s[f][0]; whi[f] = s[f][1]; }
            pend = 1;
        } else {
            // segment end: PV(j) immediately (non-overlapped; 1-2 per CTA)
#pragma unroll
            for (int kk = 0; kk < 8; kk++) {
                uint32_t aW[4] = { s[2 * kk][0], s[2 * kk][1],
                                  s[2 * kk + 1][0], s[2 * kk + 1][1] };
#pragma unroll
                for (int G = 0; G < 8; G++) {
                    int rz = kk * 16 + ((sub & 1) << 3) + l7;
                    int ch = 2 * G + (sub >> 1);
                    uint32_t r0, r1, r2, r3;
                    ldsm4t(r0, r1, r2, r3, eb + rz * 256 + ((ch ^ (rz & 7)) << 4));
                    mma16816(o[2 * G], aW, r0, r1);
                    mma16816(o[2 * G + 1], aW, r2, r3);
                }
            }
            pend = 0;
            // flush segment partials
            float s0 = ssum0, s1 = ssum1;
            int c0 = cnt0, c1 = cnt1;
            s0 += __shfl_xor_sync(0xffffffffu, s0, 1);
            s0 += __shfl_xor_sync(0xffffffffu, s0, 2);
            s1 += __shfl_xor_sync(0xffffffffu, s1, 1);
            s1 += __shfl_xor_sync(0xffffffffu, s1, 2);
            c0 += __shfl_xor_sync(0xffffffffu, c0, 1);
            c0 += __shfl_xor_sync(0xffffffffu, c0, 2);
            c1 += __shfl_xor_sync(0xffffffffu, c1, 1);
            c1 += __shfl_xor_sync(0xffffffffu, c1, 2);
            const int slot = (cta << 1) | seg;
            const int r0i = wrow0 + g;
            if (tq == 0) {
                int idx = slot * 128 + r0i;
                g_pss[idx] = s0;     g_pcnt[idx] = c0 >> 3;
                g_pss[idx + 8] = s1; g_pcnt[idx + 8] = c1 >> 3;
            }
            float* p0 = g_pacc + (size_t)slot * (128 * D_DIM) + r0i * D_DIM;
            float* p1 = p0 + 8 * D_DIM;
            const int t2 = tq * 2;
#pragma unroll
            for (int f = 0; f < 16; f++) {
                *reinterpret_cast<float2*>(&p0[f * 8 + t2]) = make_float2(o[f][0], o[f][1]);
                *reinterpret_cast<float2*>(&p1[f * 8 + t2]) = make_float2(o[f][2], o[f][3]);
            }
            if (cross) {
                seg = 1;
                bt = (j + 1) >> 8;
#pragma unroll
                for (int it = 0; it < 8; it++) {
                    int f = it * THREADS + tid, r = f >> 4, c = f & 15;
                    const float4* sp = reinterpret_cast<const float4*>(
                        &ctx[(size_t)((bt << 7) + r) * D_DIM + c * 8]);
                    float4 v0 = sp[0], v1 = sp[1];
                    uint4 oo;
                    oo.x = pk(v0.x * SCALE2, v0.y * SCALE2);
                    oo.y = pk(v0.z * SCALE2, v0.w * SCALE2);
                    oo.z = pk(v1.x * SCALE2, v1.y * SCALE2);
                    oo.w = pk(v1.z * SCALE2, v1.w * SCALE2);
                    *reinterpret_cast<uint4*>(smem + SM_CTX + r * 256 + ((c ^ (r & 7)) << 4)) = oo;
                }
                __syncthreads();
#pragma unroll
                for (int kk = 0; kk < 8; kk++) {
                    int rm = wrow0 + ((sub & 1) << 3) + l7;
                    int ch = 2 * kk + (sub >> 1);
                    ldsm4(aCtx[kk][0], aCtx[kk][1], aCtx[kk][2], aCtx[kk][3],
                          sb + SM_CTX + rm * 256 + ((ch ^ (rm & 7)) << 4));
                }
#pragma unroll
                for (int i = 0; i < 16; i++)
#pragma unroll
                    for (int jx = 0; jx < 4; jx++) o[i][jx] = 0.f;
                ssum0 = ssum1 = 0.f;
                cnt0 = cnt1 = 0;
            }
        }
        es = (es + 1) & 3;
        ms = (ms == 2) ? 0 : ms + 1;
    }
}

// vectorized: one float4 of d per thread; ss/cnt amortized over 4 elements
__global__ void stage2_finalize(float* __restrict__ out)
{
    int i4 = blockIdx.x * blockDim.x + threadIdx.x;   // 32768 threads
    if (i4 >= B_DIM * D_DIM / 4) return;
    int b = i4 >> 5, d4 = (i4 & 31) * 4;
    int bt = b >> 7, rb = b & 127;
    int zlo = bt << 8, zhi1 = zlo + 255;

    int k0 = (zlo * NCTA) / NJOBS;
    if ((((k0 + 1) * NJOBS) / NCTA) <= zlo) k0++;
    int kh = (zhi1 * NCTA) / NJOBS;
    if ((((kh + 1) * NJOBS) / NCTA) <= zhi1) kh++;

    float4 acc = make_float4(0.f, 0.f, 0.f, 0.f);
    float ss = 0.f;
    int cc = 0;
#pragma unroll
    for (int u = 0; u < 21; u++) {
        int k = k0 + u;
        bool valid = (k <= kh);
        int kc = valid ? k : kh;
        int jj0 = (kc * NJOBS) / NCTA;
        int slot = 2 * kc + (((jj0 >> 8) == bt) ? 0 : 1);
        float4 a = *reinterpret_cast<const float4*>(
            &g_pacc[(size_t)slot * (128 * D_DIM) + rb * D_DIM + d4]);
        float s = g_pss[slot * 128 + rb];
        int c = g_pcnt[slot * 128 + rb];
        if (valid) {
            acc.x += a.x; acc.y += a.y; acc.z += a.z; acc.w += a.w;
            ss += s; cc += c;
        }
    }
    float inv = (ss > 0.f) ? 1.f / (ss * (float)cc) : 0.f;
    float4 r = make_float4(acc.x * inv, acc.y * inv, acc.z * inv, acc.w * inv);
    *reinterpret_cast<float4*>(&out[b * D_DIM + d4]) = r;
}

extern "C" void kernel_launch(void* const* d_in, const int* in_sizes, int n_in,
                              void* d_out, int out_size)
{
    const int*   zs  = (const int*)d_in[0];
    const float* ctx = (const float*)d_in[1];
    const float* emb = (const float*)d_in[2];
    float* out = (float*)d_out;

    conv_emb<<<2048, 256>>>(emb);
    cudaFuncSetAttribute(stage2_mma, cudaFuncAttributeMaxDynamicSharedMemorySize, SM_TOTAL);
    stage2_mma<<<NCTA, THREADS, SM_TOTAL>>>(zs, ctx);
    stage2_finalize<<<B_DIM * D_DIM / 4 / 256, 256>>>(out);
}

// round 15
// speedup vs baseline: 1.0217x; 1.0217x over previous
#include <cuda_runtime.h>
#include <cuda_fp16.h>
#include <cstdint>

#define B_DIM 1024
#define Z_DIM 32768
#define D_DIM 128

constexpr int NCTA = 148;     // one exact wave
constexpr int NJOBS = 2048;   // job j -> (bt = j>>8, zt = j&255)
constexpr int THREADS = 256;  // 8 warps x 16-row bands
constexpr float SCALE2 = 0.088388347648318447f * 1.4426950408889634f;  // rsqrt(128)*log2(e)

constexpr int MASK_P = 132;
constexpr int MASK_BUF = 128 * MASK_P;          // 16896
// smem: 3-stage emb fp16, ctx fp16, 3-stage byte mask
constexpr int SM_EMB  = 0;                      // 3 x 32768
constexpr int SM_CTX  = 98304;                  // 32768
constexpr int SM_MASK = 131072;                 // 3 x 16896
constexpr int SM_TOTAL = SM_MASK + 3 * MASK_BUF;   // 181760

__device__ uint32_t g_emb16[Z_DIM * D_DIM / 2];    // fp16x2 table, 8 MB
// per-segment partials: slot = 2*cta + seg
__device__ float g_pacc[2 * NCTA * 128 * D_DIM];   // 19.4 MB
__device__ float g_pss[2 * NCTA * 128];
__device__ int   g_pcnt[2 * NCTA * 128];

__device__ __forceinline__ uint32_t smem_u32(const void* p) {
    uint32_t a;
    asm("{ .reg .u64 t; cvta.to.shared.u64 t, %1; cvt.u32.u64 %0, t; }" : "=r"(a) : "l"(p));
    return a;
}
__device__ __forceinline__ uint32_t pk(float lo, float hi) {
    uint32_t r;
    asm("cvt.rn.f16x2.f32 %0, %1, %2;" : "=r"(r) : "f"(hi), "f"(lo));
    return r;
}
__device__ __forceinline__ uint32_t ex2h2(uint32_t x) {
    uint32_t y;
    asm("ex2.approx.f16x2 %0, %1;" : "=r"(y) : "r"(x));
    return y;
}
__device__ __forceinline__ uint32_t hadd2(uint32_t a, uint32_t b) {
    uint32_t y;
    asm("add.rn.f16x2 %0, %1, %2;" : "=r"(y) : "r"(a), "r"(b));
    return y;
}
__device__ __forceinline__ uint32_t prmt_sign(uint32_t m) {
    uint32_t y;
    asm("prmt.b32 %0, %1, 0, 0x9988;" : "=r"(y) : "r"(m));
    return y;
}
__device__ __forceinline__ void ldsm4(uint32_t& r0, uint32_t& r1, uint32_t& r2, uint32_t& r3,
                                      uint32_t a) {
    asm volatile("ldmatrix.sync.aligned.m8n8.x4.shared.b16 {%0,%1,%2,%3}, [%4];"
                 : "=r"(r0), "=r"(r1), "=r"(r2), "=r"(r3) : "r"(a));
}
__device__ __forceinline__ void ldsm4t(uint32_t& r0, uint32_t& r1, uint32_t& r2, uint32_t& r3,
                                       uint32_t a) {
    asm volatile("ldmatrix.sync.aligned.m8n8.x4.trans.shared.b16 {%0,%1,%2,%3}, [%4];"
                 : "=r"(r0), "=r"(r1), "=r"(r2), "=r"(r3) : "r"(a));
}
__device__ __forceinline__ void mma16816(float* c, const uint32_t* a, uint32_t b0, uint32_t b1) {
    asm volatile("mma.sync.aligned.m16n8k16.row.col.f32.f16.f16.f32 "
                 "{%0,%1,%2,%3}, {%4,%5,%6,%7}, {%8,%9}, {%0,%1,%2,%3};"
                 : "+f"(c[0]), "+f"(c[1]), "+f"(c[2]), "+f"(c[3])
                 : "r"(a[0]), "r"(a[1]), "r"(a[2]), "r"(a[3]), "r"(b0), "r"(b1));
}
__device__ __forceinline__ void mma16816h(uint32_t* c, const uint32_t* a, uint32_t b0, uint32_t b1) {
    asm volatile("mma.sync.aligned.m16n8k16.row.col.f16.f16.f16.f16 "
                 "{%0,%1}, {%2,%3,%4,%5}, {%6,%7}, {%0,%1};"
                 : "+r"(c[0]), "+r"(c[1])
                 : "r"(a[0]), "r"(a[1]), "r"(a[2]), "r"(a[3]), "r"(b0), "r"(b1));
}
__device__ __forceinline__ void cp16(uint32_t dst, const void* src) {
    asm volatile("cp.async.cg.shared.global [%0], [%1], 16;" :: "r"(dst), "l"(src));
}

// fp32 table -> fp16 (linear layout), one uint4 per thread (measured-best shape)
__global__ void conv_emb(const float* __restrict__ emb) {
    int f = blockIdx.x * 256 + threadIdx.x;          // 524288 threads
    const float4* s = reinterpret_cast<const float4*>(emb) + (size_t)f * 2;
    float4 v0 = s[0], v1 = s[1];
    uint4 o;
    o.x = pk(v0.x, v0.y); o.y = pk(v0.z, v0.w);
    o.z = pk(v1.x, v1.y); o.w = pk(v1.z, v1.w);
    reinterpret_cast<uint4*>(g_emb16)[f] = o;
}

__global__ __launch_bounds__(THREADS, 1) void stage2_mma(
    const int* __restrict__ zs, const float* __restrict__ ctx)
{
    extern __shared__ __align__(128) char smem[];
    const uint32_t sb = smem_u32(smem);
    const int tid = threadIdx.x, w = tid >> 5, lane = tid & 31;
    const int cta = blockIdx.x;
    const int j0 = (cta * NJOBS) / NCTA;
    const int j1 = ((cta + 1) * NJOBS) / NCTA;
    const int wrow0 = w * 16;
    const int sub = lane >> 3, l7 = lane & 7;
    const int g = lane >> 2, tq = lane & 3;
    const char* embg = reinterpret_cast<const char*>(g_emb16);

    int bt = j0 >> 8;
    int seg = 0;

    // ---- prologue: emb(j0) -> stage0 (cp.async), mask(j0) -> stage0, ctx staged
#pragma unroll
    for (int it = 0; it < 8; it++) {
        int f = it * THREADS + tid, r = f >> 4, c = f & 15;
        cp16(sb + SM_EMB + r * 256 + ((c ^ (r & 7)) << 4),
             embg + ((size_t)(j0 & 255) * 128 + r) * 256 + c * 16);
    }
    asm volatile("cp.async.commit_group;" ::: "memory");
#pragma unroll
    for (int it = 0; it < 16; it++) {
        int row = it * 8 + w;
        int4 m = *reinterpret_cast<const int4*>(
            &zs[(size_t)((bt << 7) + row) * Z_DIM + (j0 & 255) * 128 + lane * 4]);
        uchar4 mb;
        mb.x = (m.x > 0) ? 0xFFu : 0u; mb.y = (m.y > 0) ? 0xFFu : 0u;
        mb.z = (m.z > 0) ? 0xFFu : 0u; mb.w = (m.w > 0) ? 0xFFu : 0u;
        *reinterpret_cast<uchar4*>(smem + SM_MASK + row * MASK_P + lane * 4) = mb;
    }
#pragma unroll
    for (int it = 0; it < 8; it++) {
        int f = it * THREADS + tid, r = f >> 4, c = f & 15;
        const float4* s = reinterpret_cast<const float4*>(
            &ctx[(size_t)((bt << 7) + r) * D_DIM + c * 8]);
        float4 v0 = s[0], v1 = s[1];
        uint4 o;
        o.x = pk(v0.x * SCALE2, v0.y * SCALE2); o.y = pk(v0.z * SCALE2, v0.w * SCALE2);
        o.z = pk(v1.x * SCALE2, v1.y * SCALE2); o.w = pk(v1.z * SCALE2, v1.w * SCALE2);
        *reinterpret_cast<uint4*>(smem + SM_CTX + r * 256 + ((c ^ (r & 7)) << 4)) = o;
    }
    __syncthreads();

    uint32_t aCtx[8][4];
#pragma unroll
    for (int kk = 0; kk < 8; kk++) {
        int rm = wrow0 + ((sub & 1) << 3) + l7;
        int ch = 2 * kk + (sub >> 1);
        ldsm4(aCtx[kk][0], aCtx[kk][1], aCtx[kk][2], aCtx[kk][3],
              sb + SM_CTX + rm * 256 + ((ch ^ (rm & 7)) << 4));
    }

    float o[16][4];
#pragma unroll
    for (int i = 0; i < 16; i++)
#pragma unroll
        for (int jx = 0; jx < 4; jx++) o[i][jx] = 0.f;
    float ssum0 = 0.f, ssum1 = 0.f;
    int cnt0 = 0, cnt1 = 0;
    int cur = 0;

    for (int j = j0; j < j1; j++) {
        const int nxt = (cur == 2) ? 0 : cur + 1;
        // ---- prefetch job j+1 into stage nxt (1-ahead: laggard reads cur, disjoint)
        if (j + 1 < j1) {
            int ztn = (j + 1) & 255;
#pragma unroll
            for (int it = 0; it < 8; it++) {
                int f = it * THREADS + tid, r = f >> 4, c = f & 15;
                cp16(sb + SM_EMB + nxt * 32768 + r * 256 + ((c ^ (r & 7)) << 4),
                     embg + ((size_t)ztn * 128 + r) * 256 + c * 16);
            }
        }
        asm volatile("cp.async.commit_group;" ::: "memory");
        if (j + 1 < j1) {
            int btn = (j + 1) >> 8, ztn = (j + 1) & 255;
            char* mdst = smem + SM_MASK + nxt * MASK_BUF;
#pragma unroll
            for (int it = 0; it < 16; it++) {
                int row = it * 8 + w;
                int4 m = *reinterpret_cast<const int4*>(
                    &zs[(size_t)((btn << 7) + row) * Z_DIM + ztn * 128 + lane * 4]);
                uchar4 mb;
                mb.x = (m.x > 0) ? 0xFFu : 0u; mb.y = (m.y > 0) ? 0xFFu : 0u;
                mb.z = (m.z > 0) ? 0xFFu : 0u; mb.w = (m.w > 0) ? 0xFFu : 0u;
                *reinterpret_cast<uchar4*>(&mdst[row * MASK_P + lane * 4]) = mb;
            }
        }

        asm volatile("cp.async.wait_group 1;" ::: "memory");
        __syncthreads();   // single barrier per job

        const uint32_t eb = sb + SM_EMB + cur * 32768;
        const unsigned char* mask_s =
            reinterpret_cast<const unsigned char*>(smem + SM_MASK + cur * MASK_BUF);

        // S = ctx @ emb^T, fp16 accumulate (C frag already PV's A layout)
        uint32_t s[16][2];
#pragma unroll
        for (int i = 0; i < 16; i++) { s[i][0] = 0u; s[i][1] = 0u; }
#pragma unroll
        for (int kk = 0; kk < 8; kk++) {
#pragma unroll
            for (int G = 0; G < 8; G++) {
                int rz = G * 16 + ((sub >> 1) << 3) + l7;
                int ch = 2 * kk + (sub & 1);
                uint32_t r0, r1, r2, r3;
                ldsm4(r0, r1, r2, r3, eb + rz * 256 + ((ch ^ (rz & 7)) << 4));
                mma16816h(s[2 * G], aCtx[kk], r0, r1);
                mma16816h(s[2 * G + 1], aCtx[kk], r2, r3);
            }
        }

        // packed-f16 masked softmax weights
        const unsigned char* mrow0 = &mask_s[(wrow0 + g) * MASK_P];
        const unsigned char* mrow1 = mrow0 + 8 * MASK_P;
        uint32_t sa0 = 0, sa1 = 0;
#pragma unroll
        for (int f = 0; f < 16; f++) {
            int zb = 8 * f + 2 * tq;
            uint32_t m0 = *reinterpret_cast<const unsigned short*>(&mrow0[zb]);
            uint32_t m1 = *reinterpret_cast<const unsigned short*>(&mrow1[zb]);
            cnt0 += __popc(m0);
            cnt1 += __popc(m1);
            s[f][0] = ex2h2(s[f][0]) & prmt_sign(m0);
            s[f][1] = ex2h2(s[f][1]) & prmt_sign(m1);
            sa0 = hadd2(sa0, s[f][0]);
            sa1 = hadd2(sa1, s[f][1]);
        }
        {
            __half2 h0 = *reinterpret_cast<__half2*>(&sa0);
            __half2 h1 = *reinterpret_cast<__half2*>(&sa1);
            ssum0 += __low2float(h0) + __high2float(h0);
            ssum1 += __low2float(h1) + __high2float(h1);
        }

        // O += W @ emb (fp32 accumulate)
#pragma unroll
        for (int kk = 0; kk < 8; kk++) {
            uint32_t aW[4] = { s[2 * kk][0], s[2 * kk][1],
                              s[2 * kk + 1][0], s[2 * kk + 1][1] };
#pragma unroll
            for (int G = 0; G < 8; G++) {
                int rz = kk * 16 + ((sub & 1) << 3) + l7;
                int ch = 2 * G + (sub >> 1);
                uint32_t r0, r1, r2, r3;
                ldsm4t(r0, r1, r2, r3, eb + rz * 256 + ((ch ^ (rz & 7)) << 4));
                mma16816(o[2 * G], aW, r0, r1);
                mma16816(o[2 * G + 1], aW, r2, r3);
            }
        }

        // ---- segment flush (uniform branch per CTA)
        bool lastjob = (j + 1 == j1);
        bool cross = !lastjob && (((j + 1) >> 8) != bt);
        if (lastjob || cross) {
            float s0 = ssum0, s1 = ssum1;
            int c0 = cnt0, c1 = cnt1;
            s0 += __shfl_xor_sync(0xffffffffu, s0, 1);
            s0 += __shfl_xor_sync(0xffffffffu, s0, 2);
            s1 += __shfl_xor_sync(0xffffffffu, s1, 1);
            s1 += __shfl_xor_sync(0xffffffffu, s1, 2);
            c0 += __shfl_xor_sync(0xffffffffu, c0, 1);
            c0 += __shfl_xor_sync(0xffffffffu, c0, 2);
            c1 += __shfl_xor_sync(0xffffffffu, c1, 1);
            c1 += __shfl_xor_sync(0xffffffffu, c1, 2);
            const int slot = (cta << 1) | seg;
            const int r0i = wrow0 + g;
            if (tq == 0) {
                int idx = slot * 128 + r0i;
                g_pss[idx] = s0;     g_pcnt[idx] = c0 >> 3;
                g_pss[idx + 8] = s1; g_pcnt[idx + 8] = c1 >> 3;
            }
            float* p0 = g_pacc + (size_t)slot * (128 * D_DIM) + r0i * D_DIM;
            float* p1 = p0 + 8 * D_DIM;
            const int t2 = tq * 2;
#pragma unroll
            for (int f = 0; f < 16; f++) {
                *reinterpret_cast<float2*>(&p0[f * 8 + t2]) = make_float2(o[f][0], o[f][1]);
                *reinterpret_cast<float2*>(&p1[f * 8 + t2]) = make_float2(o[f][2], o[f][3]);
            }
            if (cross) {
                seg = 1;
                bt = (j + 1) >> 8;
#pragma unroll
                for (int it = 0; it < 8; it++) {
                    int f = it * THREADS + tid, r = f >> 4, c = f & 15;
                    const float4* sp = reinterpret_cast<const float4*>(
                        &ctx[(size_t)((bt << 7) + r) * D_DIM + c * 8]);
                    float4 v0 = sp[0], v1 = sp[1];
                    uint4 oo;
                    oo.x = pk(v0.x * SCALE2, v0.y * SCALE2);
                    oo.y = pk(v0.z * SCALE2, v0.w * SCALE2);
                    oo.z = pk(v1.x * SCALE2, v1.y * SCALE2);
                    oo.w = pk(v1.z * SCALE2, v1.w * SCALE2);
                    *reinterpret_cast<uint4*>(smem + SM_CTX + r * 256 + ((c ^ (r & 7)) << 4)) = oo;
                }
                __syncthreads();
#pragma unroll
                for (int kk = 0; kk < 8; kk++) {
                    int rm = wrow0 + ((sub & 1) << 3) + l7;
                    int ch = 2 * kk + (sub >> 1);
                    ldsm4(aCtx[kk][0], aCtx[kk][1], aCtx[kk][2], aCtx[kk][3],
                          sb + SM_CTX + rm * 256 + ((ch ^ (rm & 7)) << 4));
                }
#pragma unroll
                for (int i = 0; i < 16; i++)
#pragma unroll
                    for (int jx = 0; jx < 4; jx++) o[i][jx] = 0.f;
                ssum0 = ssum1 = 0.f;
                cnt0 = cnt1 = 0;
            }
        }
        cur = nxt;
    }
}

// vectorized: one float4 of d per thread; ss/cnt amortized over 4 elements
__global__ void stage2_finalize(float* __restrict__ out)
{
    int i4 = blockIdx.x * blockDim.x + threadIdx.x;   // 32768 threads
    if (i4 >= B_DIM * D_DIM / 4) return;
    int b = i4 >> 5, d4 = (i4 & 31) * 4;
    int bt = b >> 7, rb = b & 127;
    int zlo = bt << 8, zhi1 = zlo + 255;

    int k0 = (zlo * NCTA) / NJOBS;
    if ((((k0 + 1) * NJOBS) / NCTA) <= zlo) k0++;
    int kh = (zhi1 * NCTA) / NJOBS;
    if ((((kh + 1) * NJOBS) / NCTA) <= zhi1) kh++;

    float4 acc = make_float4(0.f, 0.f, 0.f, 0.f);
    float ss = 0.f;
    int cc = 0;
#pragma unroll
    for (int u = 0; u < 21; u++) {
        int k = k0 + u;
        bool valid = (k <= kh);
        int kc = valid ? k : kh;
        int jj0 = (kc * NJOBS) / NCTA;
        int slot = 2 * kc + (((jj0 >> 8) == bt) ? 0 : 1);
        float4 a = *reinterpret_cast<const float4*>(
            &g_pacc[(size_t)slot * (128 * D_DIM) + rb * D_DIM + d4]);
        float s = g_pss[slot * 128 + rb];
        int c = g_pcnt[slot * 128 + rb];
        if (valid) {
            acc.x += a.x; acc.y += a.y; acc.z += a.z; acc.w += a.w;
            ss += s; cc += c;
        }
    }
    float inv = (ss > 0.f) ? 1.f / (ss * (float)cc) : 0.f;
    float4 r = make_float4(acc.x * inv, acc.y * inv, acc.z * inv, acc.w * inv);
    *reinterpret_cast<float4*>(&out[b * D_DIM + d4]) = r;
}

extern "C" void kernel_launch(void* const* d_in, const int* in_sizes, int n_in,
                              void* d_out, int out_size)
{
    const int*   zs  = (const int*)d_in[0];
    const float* ctx = (const float*)d_in[1];
    const float* emb = (const float*)d_in[2];
    float* out = (float*)d_out;

    conv_emb<<<2048, 256>>>(emb);
    cudaFuncSetAttribute(stage2_mma, cudaFuncAttributeMaxDynamicSharedMemorySize, SM_TOTAL);
    stage2_mma<<<NCTA, THREADS, SM_TOTAL>>>(zs, ctx);
    stage2_finalize<<<B_DIM * D_DIM / 4 / 256, 256>>>(out);
}

// round 16
// speedup vs baseline: 1.0280x; 1.0062x over previous
#include <cuda_runtime.h>
#include <cuda_fp16.h>
#include <cstdint>

#define B_DIM 1024
#define Z_DIM 32768
#define D_DIM 128

constexpr int NCTA = 148;     // one exact wave (1 CTA/SM, smem-forced) -> barrier safe
constexpr int NJOBS = 2048;   // job j -> (bt = j>>8, zt = j&255)
constexpr int THREADS = 256;  // 8 warps x 16-row bands
constexpr float SCALE2 = 0.088388347648318447f * 1.4426950408889634f;  // rsqrt(128)*log2(e)

constexpr int MASK_P = 132;
constexpr int MASK_BUF = 128 * MASK_P;          // 16896
// smem: 3-stage emb fp16, ctx fp16, 3-stage byte mask
constexpr int SM_EMB  = 0;                      // 3 x 32768
constexpr int SM_CTX  = 98304;                  // 32768
constexpr int SM_MASK = 131072;                 // 3 x 16896
constexpr int SM_TOTAL = SM_MASK + 3 * MASK_BUF;   // 181760

constexpr int CONV_N = Z_DIM * D_DIM / 8;       // 524288 uint4 outputs

__device__ uint32_t g_emb16[Z_DIM * D_DIM / 2];    // fp16x2 table, 8 MB
__device__ unsigned g_bar;                          // monotonic ticket barrier (replay-safe)
// per-segment partials: slot = 2*cta + seg
__device__ float g_pacc[2 * NCTA * 128 * D_DIM];   // 19.4 MB
__device__ float g_pss[2 * NCTA * 128];
__device__ int   g_pcnt[2 * NCTA * 128];

__device__ __forceinline__ uint32_t smem_u32(const void* p) {
    uint32_t a;
    asm("{ .reg .u64 t; cvta.to.shared.u64 t, %1; cvt.u32.u64 %0, t; }" : "=r"(a) : "l"(p));
    return a;
}
__device__ __forceinline__ uint32_t pk(float lo, float hi) {
    uint32_t r;
    asm("cvt.rn.f16x2.f32 %0, %1, %2;" : "=r"(r) : "f"(hi), "f"(lo));
    return r;
}
__device__ __forceinline__ uint32_t ex2h2(uint32_t x) {
    uint32_t y;
    asm("ex2.approx.f16x2 %0, %1;" : "=r"(y) : "r"(x));
    return y;
}
__device__ __forceinline__ uint32_t hadd2(uint32_t a, uint32_t b) {
    uint32_t y;
    asm("add.rn.f16x2 %0, %1, %2;" : "=r"(y) : "r"(a), "r"(b));
    return y;
}
__device__ __forceinline__ uint32_t prmt_sign(uint32_t m) {
    uint32_t y;
    asm("prmt.b32 %0, %1, 0, 0x9988;" : "=r"(y) : "r"(m));
    return y;
}
__device__ __forceinline__ void ldsm4(uint32_t& r0, uint32_t& r1, uint32_t& r2, uint32_t& r3,
                                      uint32_t a) {
    asm volatile("ldmatrix.sync.aligned.m8n8.x4.shared.b16 {%0,%1,%2,%3}, [%4];"
                 : "=r"(r0), "=r"(r1), "=r"(r2), "=r"(r3) : "r"(a));
}
__device__ __forceinline__ void ldsm4t(uint32_t& r0, uint32_t& r1, uint32_t& r2, uint32_t& r3,
                                       uint32_t a) {
    asm volatile("ldmatrix.sync.aligned.m8n8.x4.trans.shared.b16 {%0,%1,%2,%3}, [%4];"
                 : "=r"(r0), "=r"(r1), "=r"(r2), "=r"(r3) : "r"(a));
}
__device__ __forceinline__ void mma16816(float* c, const uint32_t* a, uint32_t b0, uint32_t b1) {
    asm volatile("mma.sync.aligned.m16n8k16.row.col.f32.f16.f16.f32 "
                 "{%0,%1,%2,%3}, {%4,%5,%6,%7}, {%8,%9}, {%0,%1,%2,%3};"
                 : "+f"(c[0]), "+f"(c[1]), "+f"(c[2]), "+f"(c[3])
                 : "r"(a[0]), "r"(a[1]), "r"(a[2]), "r"(a[3]), "r"(b0), "r"(b1));
}
__device__ __forceinline__ void mma16816h(uint32_t* c, const uint32_t* a, uint32_t b0, uint32_t b1) {
    asm volatile("mma.sync.aligned.m16n8k16.row.col.f16.f16.f16.f16 "
                 "{%0,%1}, {%2,%3,%4,%5}, {%6,%7}, {%0,%1};"
                 : "+r"(c[0]), "+r"(c[1])
                 : "r"(a[0]), "r"(a[1]), "r"(a[2]), "r"(a[3]), "r"(b0), "r"(b1));
}
__device__ __forceinline__ void cp16(uint32_t dst, const void* src) {
    asm volatile("cp.async.cg.shared.global [%0], [%1], 16;" :: "r"(dst), "l"(src));
}

__global__ __launch_bounds__(THREADS, 1) void stage2_mma(
    const int* __restrict__ zs, const float* __restrict__ ctx, const float* __restrict__ emb)
{
    extern __shared__ __align__(128) char smem[];
    const uint32_t sb = smem_u32(smem);
    const int tid = threadIdx.x, w = tid >> 5, lane = tid & 31;
    const int cta = blockIdx.x;
    const int j0 = (cta * NJOBS) / NCTA;
    const int j1 = ((cta + 1) * NJOBS) / NCTA;
    const int wrow0 = w * 16;
    const int sub = lane >> 3, l7 = lane & 7;
    const int g = lane >> 2, tq = lane & 3;
    const char* embg = reinterpret_cast<const char*>(g_emb16);

    int bt = j0 >> 8;
    int seg = 0;

    // ---- phase 0: convert this CTA's 1/148 slice of the fp32 table to fp16
    {
        int i0 = (cta * CONV_N) / NCTA;
        int i1 = ((cta + 1) * CONV_N) / NCTA;
        for (int i = i0 + tid; i < i1; i += THREADS) {
            const float4* s = reinterpret_cast<const float4*>(emb) + (size_t)i * 2;
            float4 v0 = s[0], v1 = s[1];
            uint4 o;
            o.x = pk(v0.x, v0.y); o.y = pk(v0.z, v0.w);
            o.z = pk(v1.x, v1.y); o.w = pk(v1.z, v1.w);
            reinterpret_cast<uint4*>(g_emb16)[i] = o;
        }
    }
    __threadfence();
    __syncthreads();   // all conversion writes issued + fenced before arrival
    __shared__ unsigned s_t;
    if (tid == 0) s_t = atomicAdd(&g_bar, 1u);

    // ---- overlap with barrier: stage mask(j0) + ctx (independent of g_emb16)
#pragma unroll
    for (int it = 0; it < 16; it++) {
        int row = it * 8 + w;
        int4 m = *reinterpret_cast<const int4*>(
            &zs[(size_t)((bt << 7) + row) * Z_DIM + (j0 & 255) * 128 + lane * 4]);
        uchar4 mb;
        mb.x = (m.x > 0) ? 0xFFu : 0u; mb.y = (m.y > 0) ? 0xFFu : 0u;
        mb.z = (m.z > 0) ? 0xFFu : 0u; mb.w = (m.w > 0) ? 0xFFu : 0u;
        *reinterpret_cast<uchar4*>(smem + SM_MASK + row * MASK_P + lane * 4) = mb;
    }
#pragma unroll
    for (int it = 0; it < 8; it++) {
        int f = it * THREADS + tid, r = f >> 4, c = f & 15;
        const float4* s = reinterpret_cast<const float4*>(
            &ctx[(size_t)((bt << 7) + r) * D_DIM + c * 8]);
        float4 v0 = s[0], v1 = s[1];
        uint4 o;
        o.x = pk(v0.x * SCALE2, v0.y * SCALE2); o.y = pk(v0.z * SCALE2, v0.w * SCALE2);
        o.z = pk(v1.x * SCALE2, v1.y * SCALE2); o.w = pk(v1.z * SCALE2, v1.w * SCALE2);
        *reinterpret_cast<uint4*>(smem + SM_CTX + r * 256 + ((c ^ (r & 7)) << 4)) = o;
    }

    // ---- grid barrier: spin (tid0) until all 148 CTAs of THIS launch arrived
    if (tid == 0) {
        unsigned target = (s_t / NCTA + 1u) * NCTA;
        while (atomicAdd(&g_bar, 0u) < target) { }
    }
    __syncthreads();
    __threadfence();   // acquire: g_emb16 writes from all CTAs now visible

    // ---- prologue: emb(j0) -> stage0 (cp.async)
#pragma unroll
    for (int it = 0; it < 8; it++) {
        int f = it * THREADS + tid, r = f >> 4, c = f & 15;
        cp16(sb + SM_EMB + r * 256 + ((c ^ (r & 7)) << 4),
             embg + ((size_t)(j0 & 255) * 128 + r) * 256 + c * 16);
    }
    asm volatile("cp.async.commit_group;" ::: "memory");
    __syncthreads();

    uint32_t aCtx[8][4];
#pragma unroll
    for (int kk = 0; kk < 8; kk++) {
        int rm = wrow0 + ((sub & 1) << 3) + l7;
        int ch = 2 * kk + (sub >> 1);
        ldsm4(aCtx[kk][0], aCtx[kk][1], aCtx[kk][2], aCtx[kk][3],
              sb + SM_CTX + rm * 256 + ((ch ^ (rm & 7)) << 4));
    }

    float o[16][4];
#pragma unroll
    for (int i = 0; i < 16; i++)
#pragma unroll
        for (int jx = 0; jx < 4; jx++) o[i][jx] = 0.f;
    float ssum0 = 0.f, ssum1 = 0.f;
    int cnt0 = 0, cnt1 = 0;
    int cur = 0;

    for (int j = j0; j < j1; j++) {
        const int nxt = (cur == 2) ? 0 : cur + 1;
        // ---- prefetch job j+1 into stage nxt (1-ahead: laggard reads cur, disjoint)
        if (j + 1 < j1) {
            int ztn = (j + 1) & 255;
#pragma unroll
            for (int it = 0; it < 8; it++) {
                int f = it * THREADS + tid, r = f >> 4, c = f & 15;
                cp16(sb + SM_EMB + nxt * 32768 + r * 256 + ((c ^ (r & 7)) << 4),
                     embg + ((size_t)ztn * 128 + r) * 256 + c * 16);
            }
        }
        asm volatile("cp.async.commit_group;" ::: "memory");
        if (j + 1 < j1) {
            int btn = (j + 1) >> 8, ztn = (j + 1) & 255;
            char* mdst = smem + SM_MASK + nxt * MASK_BUF;
#pragma unroll
            for (int it = 0; it < 16; it++) {
                int row = it * 8 + w;
                int4 m = *reinterpret_cast<const int4*>(
                    &zs[(size_t)((btn << 7) + row) * Z_DIM + ztn * 128 + lane * 4]);
                uchar4 mb;
                mb.x = (m.x > 0) ? 0xFFu : 0u; mb.y = (m.y > 0) ? 0xFFu : 0u;
                mb.z = (m.z > 0) ? 0xFFu : 0u; mb.w = (m.w > 0) ? 0xFFu : 0u;
                *reinterpret_cast<uchar4*>(&mdst[row * MASK_P + lane * 4]) = mb;
            }
        }

        asm volatile("cp.async.wait_group 1;" ::: "memory");
        __syncthreads();   // single barrier per job

        const uint32_t eb = sb + SM_EMB + cur * 32768;
        const unsigned char* mask_s =
            reinterpret_cast<const unsigned char*>(smem + SM_MASK + cur * MASK_BUF);

        // S = ctx @ emb^T, fp16 accumulate (C frag already PV's A layout)
        uint32_t s[16][2];
#pragma unroll
        for (int i = 0; i < 16; i++) { s[i][0] = 0u; s[i][1] = 0u; }
#pragma unroll
        for (int kk = 0; kk < 8; kk++) {
#pragma unroll
            for (int G = 0; G < 8; G++) {
                int rz = G * 16 + ((sub >> 1) << 3) + l7;
                int ch = 2 * kk + (sub & 1);
                uint32_t r0, r1, r2, r3;
                ldsm4(r0, r1, r2, r3, eb + rz * 256 + ((ch ^ (rz & 7)) << 4));
                mma16816h(s[2 * G], aCtx[kk], r0, r1);
                mma16816h(s[2 * G + 1], aCtx[kk], r2, r3);
            }
        }

        // packed-f16 masked softmax weights
        const unsigned char* mrow0 = &mask_s[(wrow0 + g) * MASK_P];
        const unsigned char* mrow1 = mrow0 + 8 * MASK_P;
        uint32_t sa0 = 0, sa1 = 0;
#pragma unroll
        for (int f = 0; f < 16; f++) {
            int zb = 8 * f + 2 * tq;
            uint32_t m0 = *reinterpret_cast<const unsigned short*>(&mrow0[zb]);
            uint32_t m1 = *reinterpret_cast<const unsigned short*>(&mrow1[zb]);
            cnt0 += __popc(m0);
            cnt1 += __popc(m1);
            s[f][0] = ex2h2(s[f][0]) & prmt_sign(m0);
            s[f][1] = ex2h2(s[f][1]) & prmt_sign(m1);
            sa0 = hadd2(sa0, s[f][0]);
            sa1 = hadd2(sa1, s[f][1]);
        }
        {
            __half2 h0 = *reinterpret_cast<__half2*>(&sa0);
            __half2 h1 = *reinterpret_cast<__half2*>(&sa1);
            ssum0 += __low2float(h0) + __high2float(h0);
            ssum1 += __low2float(h1) + __high2float(h1);
        }

        // O += W @ emb (fp32 accumulate)
#pragma unroll
        for (int kk = 0; kk < 8; kk++) {
            uint32_t aW[4] = { s[2 * kk][0], s[2 * kk][1],
                              s[2 * kk + 1][0], s[2 * kk + 1][1] };
#pragma unroll
            for (int G = 0; G < 8; G++) {
                int rz = kk * 16 + ((sub & 1) << 3) + l7;
                int ch = 2 * G + (sub >> 1);
                uint32_t r0, r1, r2, r3;
                ldsm4t(r0, r1, r2, r3, eb + rz * 256 + ((ch ^ (rz & 7)) << 4));
                mma16816(o[2 * G], aW, r0, r1);
                mma16816(o[2 * G + 1], aW, r2, r3);
            }
        }

        // ---- segment flush (uniform branch per CTA)
        bool lastjob = (j + 1 == j1);
        bool cross = !lastjob && (((j + 1) >> 8) != bt);
        if (lastjob || cross) {
            float s0 = ssum0, s1 = ssum1;
            int c0 = cnt0, c1 = cnt1;
            s0 += __shfl_xor_sync(0xffffffffu, s0, 1);
            s0 += __shfl_xor_sync(0xffffffffu, s0, 2);
            s1 += __shfl_xor_sync(0xffffffffu, s1, 1);
            s1 += __shfl_xor_sync(0xffffffffu, s1, 2);
            c0 += __shfl_xor_sync(0xffffffffu, c0, 1);
            c0 += __shfl_xor_sync(0xffffffffu, c0, 2);
            c1 += __shfl_xor_sync(0xffffffffu, c1, 1);
            c1 += __shfl_xor_sync(0xffffffffu, c1, 2);
            const int slot = (cta << 1) | seg;
            const int r0i = wrow0 + g;
            if (tq == 0) {
                int idx = slot * 128 + r0i;
                g_pss[idx] = s0;     g_pcnt[idx] = c0 >> 3;
                g_pss[idx + 8] = s1; g_pcnt[idx + 8] = c1 >> 3;
            }
            float* p0 = g_pacc + (size_t)slot * (128 * D_DIM) + r0i * D_DIM;
            float* p1 = p0 + 8 * D_DIM;
            const int t2 = tq * 2;
#pragma unroll
            for (int f = 0; f < 16; f++) {
                *reinterpret_cast<float2*>(&p0[f * 8 + t2]) = make_float2(o[f][0], o[f][1]);
                *reinterpret_cast<float2*>(&p1[f * 8 + t2]) = make_float2(o[f][2], o[f][3]);
            }
            if (cross) {
                seg = 1;
                bt = (j + 1) >> 8;
#pragma unroll
                for (int it = 0; it < 8; it++) {
                    int f = it * THREADS + tid, r = f >> 4, c = f & 15;
                    const float4* sp = reinterpret_cast<const float4*>(
                        &ctx[(size_t)((bt << 7) + r) * D_DIM + c * 8]);
                    float4 v0 = sp[0], v1 = sp[1];
                    uint4 oo;
                    oo.x = pk(v0.x * SCALE2, v0.y * SCALE2);
                    oo.y = pk(v0.z * SCALE2, v0.w * SCALE2);
                    oo.z = pk(v1.x * SCALE2, v1.y * SCALE2);
                    oo.w = pk(v1.z * SCALE2, v1.w * SCALE2);
                    *reinterpret_cast<uint4*>(smem + SM_CTX + r * 256 + ((c ^ (r & 7)) << 4)) = oo;
                }
                __syncthreads();
#pragma unroll
                for (int kk = 0; kk < 8; kk++) {
                    int rm = wrow0 + ((sub & 1) << 3) + l7;
                    int ch = 2 * kk + (sub >> 1);
                    ldsm4(aCtx[kk][0], aCtx[kk][1], aCtx[kk][2], aCtx[kk][3],
                          sb + SM_CTX + rm * 256 + ((ch ^ (rm & 7)) << 4));
                }
#pragma unroll
                for (int i = 0; i < 16; i++)
#pragma unroll
                    for (int jx = 0; jx < 4; jx++) o[i][jx] = 0.f;
                ssum0 = ssum1 = 0.f;
                cnt0 = cnt1 = 0;
            }
        }
        cur = nxt;
    }
}

// vectorized: one float4 of d per thread; ss/cnt amortized over 4 elements
__global__ void stage2_finalize(float* __restrict__ out)
{
    int i4 = blockIdx.x * blockDim.x + threadIdx.x;   // 32768 threads
    if (i4 >= B_DIM * D_DIM / 4) return;
    int b = i4 >> 5, d4 = (i4 & 31) * 4;
    int bt = b >> 7, rb = b & 127;
    int zlo = bt << 8, zhi1 = zlo + 255;

    int k0 = (zlo * NCTA) / NJOBS;
    if ((((k0 + 1) * NJOBS) / NCTA) <= zlo) k0++;
    int kh = (zhi1 * NCTA) / NJOBS;
    if ((((kh + 1) * NJOBS) / NCTA) <= zhi1) kh++;

    float4 acc = make_float4(0.f, 0.f, 0.f, 0.f);
    float ss = 0.f;
    int cc = 0;
#pragma unroll
    for (int u = 0; u < 21; u++) {
        int k = k0 + u;
        bool valid = (k <= kh);
        int kc = valid ? k : kh;
        int jj0 = (kc * NJOBS) / NCTA;
        int slot = 2 * kc + (((jj0 >> 8) == bt) ? 0 : 1);
        float4 a = *reinterpret_cast<const float4*>(
            &g_pacc[(size_t)slot * (128 * D_DIM) + rb * D_DIM + d4]);
        float s = g_pss[slot * 128 + rb];
        int c = g_pcnt[slot * 128 + rb];
        if (valid) {
            acc.x += a.x; acc.y += a.y; acc.z += a.z; acc.w += a.w;
            ss += s; cc += c;
        }
    }
    float inv = (ss > 0.f) ? 1.f / (ss * (float)cc) : 0.f;
    float4 r = make_float4(acc.x * inv, acc.y * inv, acc.z * inv, acc.w * inv);
    *reinterpret_cast<float4*>(&out[b * D_DIM + d4]) = r;
}

extern "C" void kernel_launch(void* const* d_in, const int* in_sizes, int n_in,
                              void* d_out, int out_size)
{
    const int*   zs  = (const int*)d_in[0];
    const float* ctx = (const float*)d_in[1];
    const float* emb = (const float*)d_in[2];
    float* out = (float*)d_out;

    cudaFuncSetAttribute(stage2_mma, cudaFuncAttributeMaxDynamicSharedMemorySize, SM_TOTAL);
    stage2_mma<<<NCTA, THREADS, SM_TOTAL>>>(zs, ctx, emb);
    stage2_finalize<<<B_DIM * D_DIM / 4 / 256, 256>>>(out);
}